// round 13
// baseline (speedup 1.0000x reference)
#include <cuda_runtime.h>
#include <cuda_fp16.h>
#include <cstdint>
#include <math.h>

// ---------------- problem constants ----------------
#define TOKENS   8192
#define DIM      1024
#define NE       8
#define TOPK     2
#define HID      2730
#define HS       2752          // padded K for GEMM2 / N for GEMM1 (43*64)
#define HP       2816          // padded row count for w1/w3 (22*128)
#define ASSIGN   (TOKENS*TOPK)
#define MAXROWS  (ASSIGN+128)
#define OUT_ELEMS ((size_t)TOKENS*DIM)

#define KC     64              // K elements per chunk (4 mma k-steps)
#define SROW   72              // smem row stride (elements) -> 144B, conflict-free ldmatrix
#define TILE_A (128*SROW*2)    // 18432 B : 128x64 fp16 tile
#define TILE_Bv (64*SROW*2)    // 9216 B  : 64x64 fp16 tile
#define G1_STAGE (TILE_A + 2*TILE_Bv)   // A + B1 + B3 = 36864
#define G1_SMEM  (3*G1_STAGE)           // 110592 (3-stage, 2 CTAs/SM = 221184)
#define G2_STAGE (2*TILE_A)             // A + B = 36864
#define G2_SMEM  (3*G2_STAGE)           // 110592

// ---------------- device scratch ----------------
__device__ int   g_counts[NE];
__device__ int   g_cursor[NE];
__device__ int   g_offsets[NE+1];
__device__ float g_probSums[NE];
__device__ int   g_eids[ASSIGN];
__device__ float g_wts[ASSIGN];
__device__ int   g_perm[ASSIGN];
__device__ int   g_slotOf[ASSIGN];
__device__ float g_slotW[ASSIGN];
__device__ __half g_x[(size_t)MAXROWS*DIM];
__device__ __half g_w1[(size_t)NE*HP*DIM];
__device__ __half g_w3[(size_t)NE*HP*DIM];
__device__ __half g_w2[(size_t)NE*DIM*HS];
__device__ __half g_h[(size_t)MAXROWS*HS];

// ---------------- helpers ----------------
__device__ __forceinline__ uint32_t smem_u32(const void* p) {
    uint32_t a;
    asm("{ .reg .u64 t; cvta.to.shared.u64 t, %1; cvt.u32.u64 %0, t; }"
        : "=r"(a) : "l"(p));
    return a;
}
__device__ __forceinline__ void cp16(uint32_t dst, const void* src) {
    asm volatile("cp.async.cg.shared.global [%0], [%1], 16;" :: "r"(dst), "l"(src));
}
#define CP_COMMIT() asm volatile("cp.async.commit_group;" ::: "memory")
#define CP_WAIT0()  asm volatile("cp.async.wait_group 0;" ::: "memory")
#define CP_WAIT1()  asm volatile("cp.async.wait_group 1;" ::: "memory")

__device__ __forceinline__ void ldsm4(uint32_t* r, uint32_t addr) {
    asm volatile("ldmatrix.sync.aligned.m8n8.x4.shared.b16 {%0,%1,%2,%3}, [%4];"
                 : "=r"(r[0]), "=r"(r[1]), "=r"(r[2]), "=r"(r[3]) : "r"(addr));
}
__device__ __forceinline__ void mma16816(float* c, const uint32_t* a, const uint32_t* b) {
    asm volatile("mma.sync.aligned.m16n8k16.row.col.f32.f16.f16.f32 "
                 "{%0,%1,%2,%3}, {%4,%5,%6,%7}, {%8,%9}, {%0,%1,%2,%3};"
                 : "+f"(c[0]), "+f"(c[1]), "+f"(c[2]), "+f"(c[3])
                 : "r"(a[0]), "r"(a[1]), "r"(a[2]), "r"(a[3]),
                   "r"(b[0]), "r"(b[1]));
}

// 128x64 fp16 tile (row-major, stride SROW) via cp.async : 1024 cp16, 4/thread
__device__ __forceinline__ void cp_tile128(uint32_t s, const __half* g,
                                           int rstride, int t) {
    #pragma unroll
    for (int i = 0; i < 4; i++) {
        int id = t + i*256;
        int row = id >> 3, c16 = id & 7;
        cp16(s + (uint32_t)row*(SROW*2) + (uint32_t)c16*16,
             (const char*)g + (size_t)row*rstride*2 + (size_t)c16*16);
    }
}
// 64x64 fp16 tile : 512 cp16, 2/thread
__device__ __forceinline__ void cp_tile64(uint32_t s, const __half* g,
                                          int rstride, int t) {
    #pragma unroll
    for (int i = 0; i < 2; i++) {
        int id = t + i*256;
        int row = id >> 3, c16 = id & 7;
        cp16(s + (uint32_t)row*(SROW*2) + (uint32_t)c16*16,
             (const char*)g + (size_t)row*rstride*2 + (size_t)c16*16);
    }
}

__device__ __forceinline__ void store2h(__half* p, __half a, __half b) {
    __half2 v; v.x = a; v.y = b;
    *reinterpret_cast<__half2*>(p) = v;
}

// ---------------- init ----------------
__global__ void init_kernel() {
    int t = threadIdx.x;
    if (t < NE) { g_counts[t] = 0; g_cursor[t] = 0; g_probSums[t] = 0.f; }
}

// ---------------- zero output (atomic-accumulation target) ----------------
__global__ void zero_out_kernel(float* __restrict__ out) {
    size_t idx = ((size_t)blockIdx.x * 256 + threadIdx.x) * 4;
    float4 z = make_float4(0.f, 0.f, 0.f, 0.f);
    *reinterpret_cast<float4*>(out + idx) = z;
}

// ---------------- router ----------------
__global__ __launch_bounds__(256) void router_kernel(const float* __restrict__ x,
                                                     const float* __restrict__ gw) {
    __shared__ float sgw[NE*DIM];
    __shared__ float sprob[8][NE];
    for (int i = threadIdx.x; i < NE*DIM; i += 256) sgw[i] = gw[i];
    __syncthreads();
    int warp = threadIdx.x >> 5, lane = threadIdx.x & 31;
    int tok = blockIdx.x * 8 + warp;
    const float* xr = x + (size_t)tok * DIM;
    float acc[NE];
    #pragma unroll
    for (int e = 0; e < NE; e++) acc[e] = 0.f;
    for (int d = lane; d < DIM; d += 32) {
        float xv = xr[d];
        #pragma unroll
        for (int e = 0; e < NE; e++) acc[e] += xv * sgw[e*DIM + d];
    }
    #pragma unroll
    for (int e = 0; e < NE; e++)
        #pragma unroll
        for (int o = 16; o > 0; o >>= 1)
            acc[e] += __shfl_xor_sync(0xffffffffu, acc[e], o);
    if (lane == 0) {
        float mx = acc[0];
        #pragma unroll
        for (int e = 1; e < NE; e++) mx = fmaxf(mx, acc[e]);
        float p[NE], s = 0.f;
        #pragma unroll
        for (int e = 0; e < NE; e++) { p[e] = expf(acc[e] - mx); s += p[e]; }
        float inv = 1.f / s;
        #pragma unroll
        for (int e = 0; e < NE; e++) p[e] *= inv;
        int i0 = 0;
        #pragma unroll
        for (int e = 1; e < NE; e++) if (p[e] > p[i0]) i0 = e;
        int i1 = (i0 == 0) ? 1 : 0;
        #pragma unroll
        for (int e = 0; e < NE; e++) if (e != i0 && p[e] > p[i1]) i1 = e;
        float ws = 1.f / (p[i0] + p[i1]);
        g_eids[2*tok]   = i0; g_wts[2*tok]   = p[i0] * ws;
        g_eids[2*tok+1] = i1; g_wts[2*tok+1] = p[i1] * ws;
        atomicAdd(&g_counts[i0], 1);
        atomicAdd(&g_counts[i1], 1);
        #pragma unroll
        for (int e = 0; e < NE; e++) sprob[warp][e] = p[e];
    }
    __syncthreads();
    if (threadIdx.x < NE) {
        float s = 0.f;
        #pragma unroll
        for (int w = 0; w < 8; w++) s += sprob[w][threadIdx.x];
        atomicAdd(&g_probSums[threadIdx.x], s);
    }
}

__global__ void offsets_kernel() {
    if (threadIdx.x == 0) {
        int s = 0;
        for (int e = 0; e < NE; e++) { g_offsets[e] = s; s += g_counts[e]; }
        g_offsets[NE] = s;
    }
}

__global__ void aux_kernel(float* out, int out_size) {
    if (threadIdx.x == 0 && (size_t)out_size > OUT_ELEMS) {
        float s = 0.f;
        for (int e = 0; e < NE; e++) {
            float d = g_probSums[e] * (1.f / TOKENS) - (1.f / NE);
            s += d * d;
        }
        out[OUT_ELEMS] = 0.01f * (s / NE);
    }
}

__global__ void scatter_kernel() {
    int tok = blockIdx.x * 256 + threadIdx.x;
    if (tok >= TOKENS) return;
    #pragma unroll
    for (int k = 0; k < TOPK; k++) {
        int e = g_eids[2*tok + k];
        int pos = atomicAdd(&g_cursor[e], 1);
        int slot = g_offsets[e] + pos;
        g_perm[slot]  = tok;
        g_slotW[slot] = g_wts[2*tok + k];
        g_slotOf[2*tok + k] = slot;
    }
}

// ---------------- conversion pre-passes ----------------
__global__ __launch_bounds__(256) void convert_w13_kernel(const float* __restrict__ w1,
                                                          const float* __restrict__ w3) {
    size_t row = blockIdx.x;            // 0..NE*HP-1
    int e = (int)(row / HP), r = (int)(row % HP);
    const float* src = (blockIdx.y == 0) ? w1 : w3;
    __half* dsth = (blockIdx.y == 0) ? g_w1 : g_w3;
    size_t dst = row * DIM + threadIdx.x * 4;
    __half h[4];
    if (r < HID) {
        float4 v = *reinterpret_cast<const float4*>(src + ((size_t)e*HID + r)*DIM + threadIdx.x*4);
        h[0] = __float2half(v.x); h[1] = __float2half(v.y);
        h[2] = __float2half(v.z); h[3] = __float2half(v.w);
    } else {
        #pragma unroll
        for (int i = 0; i < 4; i++) h[i] = __float2half(0.f);
    }
    store2h(dsth + dst, h[0], h[1]); store2h(dsth + dst + 2, h[2], h[3]);
}

__global__ __launch_bounds__(256) void convert_w2_kernel(const float* __restrict__ w2) {
    size_t row = blockIdx.x;            // 0..NE*DIM-1
    const float* src = w2 + row * HID;
    for (int c = threadIdx.x; c < HS; c += 256) {
        float v = (c < HID) ? src[c] : 0.f;
        g_w2[row*HS + c] = __float2half(v);
    }
}

// gather x rows by perm into fp16; pad slots also zero their g_h row
__global__ __launch_bounds__(256) void gather_x_kernel(const float* __restrict__ x) {
    int slot = blockIdx.x;
    size_t dst = (size_t)slot * DIM + threadIdx.x * 4;
    __half h[4];
    if (slot < ASSIGN) {
        int tok = g_perm[slot];
        float4 v = *reinterpret_cast<const float4*>(x + (size_t)tok*DIM + threadIdx.x*4);
        h[0] = __float2half(v.x); h[1] = __float2half(v.y);
        h[2] = __float2half(v.z); h[3] = __float2half(v.w);
    } else {
        #pragma unroll
        for (int i = 0; i < 4; i++) h[i] = __float2half(0.f);
        for (int c = threadIdx.x; c < HS; c += 256)     // pad rows of g_h
            g_h[(size_t)slot*HS + c] = __float2half(0.f);
    }
    store2h(g_x + dst, h[0], h[1]); store2h(g_x + dst + 2, h[2], h[3]);
}

// ---------------- GEMM1: h = silu(X W1^T) * (X W3^T) ----------------
// CTA 128x64, warps 0-3 w1 / 4-7 w3, warp tile 64x32, KC=64,
// 3-stage cp.async, one barrier per chunk, 2 CTAs/SM.
__global__ __launch_bounds__(256, 2) void gemm1_mma() {
    int e   = blockIdx.z;
    int cnt = g_counts[e];
    int m0  = blockIdx.y * 128;
    if (m0 >= cnt) return;
    int base = g_offsets[e];
    int n0   = blockIdx.x * 64;

    extern __shared__ char smem[];
    uint32_t sm = smem_u32(smem);
    int tid = threadIdx.x, wid = tid >> 5, lane = tid & 31;
    int prod = wid >> 2, wm = wid & 1, wn = (wid >> 1) & 1;

    const __half* A  = g_x  + (size_t)(base + m0) * DIM;
    const __half* B1 = g_w1 + ((size_t)e * HP + n0) * DIM;
    const __half* B3 = g_w3 + ((size_t)e * HP + n0) * DIM;

    float acc[4][4][4];
    #pragma unroll
    for (int i = 0; i < 4; i++)
        #pragma unroll
        for (int j = 0; j < 4; j++)
            #pragma unroll
            for (int r = 0; r < 4; r++) acc[i][j][r] = 0.f;

    const int NC = DIM / KC;   // 16

    // preload chunks 0,1
    #pragma unroll
    for (int pc = 0; pc < 2; pc++) {
        uint32_t sb = sm + pc * G1_STAGE;
        int k0 = pc * KC;
        cp_tile128(sb,                    A  + k0, DIM, tid);
        cp_tile64 (sb + TILE_A,           B1 + k0, DIM, tid);
        cp_tile64 (sb + TILE_A + TILE_Bv, B3 + k0, DIM, tid);
        CP_COMMIT();
    }

    for (int c = 0; c < NC; c++) {
        if (c + 1 < NC) CP_WAIT1(); else CP_WAIT0();
        __syncthreads();                    // single barrier per chunk
        if (c + 2 < NC) {
            uint32_t sb = sm + ((c + 2) % 3) * G1_STAGE;
            int k0 = (c + 2) * KC;
            cp_tile128(sb,                    A  + k0, DIM, tid);
            cp_tile64 (sb + TILE_A,           B1 + k0, DIM, tid);
            cp_tile64 (sb + TILE_A + TILE_Bv, B3 + k0, DIM, tid);
            CP_COMMIT();
        }

        uint32_t sb = sm + (c % 3) * G1_STAGE;
        uint32_t sA = sb;
        uint32_t sB = sb + TILE_A + (uint32_t)prod * TILE_Bv;

        #pragma unroll
        for (int ks = 0; ks < 4; ks++) {
            int kk = ks * 16;
            uint32_t aoff = (uint32_t)(wm*64 + (lane & 15)) * (SROW*2)
                          + (uint32_t)(kk + (lane >> 4) * 8) * 2;
            uint32_t af[4][4];
            #pragma unroll
            for (int mi = 0; mi < 4; mi++)
                ldsm4(af[mi], sA + aoff + mi*16*(SROW*2));
            uint32_t boff = (uint32_t)(wn*32 + ((lane >> 4) & 1)*8 + (lane & 7)) * (SROW*2)
                          + (uint32_t)(kk + ((lane >> 3) & 1)*8) * 2;
            uint32_t bf[8];
            ldsm4(&bf[0], sB + boff);
            ldsm4(&bf[4], sB + boff + 16*(SROW*2));
            #pragma unroll
            for (int mi = 0; mi < 4; mi++)
                #pragma unroll
                for (int ni = 0; ni < 4; ni++)
                    mma16816(acc[mi][ni], af[mi], &bf[ni*2]);
        }
    }

    // protect last-chunk smem reads, then exchange w3 product through smem
    __syncthreads();
    float* xch = reinterpret_cast<float*>(smem);   // 128 x 66 f32 = 33792 B
    int gid = lane >> 2, tig = lane & 3;
    if (prod == 1) {
        #pragma unroll
        for (int mi = 0; mi < 4; mi++)
            #pragma unroll
            for (int p = 0; p < 2; p++) {
                int ml = wm*64 + mi*16 + gid + p*8;
                #pragma unroll
                for (int ni = 0; ni < 4; ni++) {
                    int nl = wn*32 + ni*8 + tig*2;
                    *reinterpret_cast<float2*>(xch + ml*66 + nl) =
                        make_float2(acc[mi][ni][2*p], acc[mi][ni][2*p+1]);
                }
            }
    }
    __syncthreads();
    if (prod == 0) {
        #pragma unroll
        for (int mi = 0; mi < 4; mi++)
            #pragma unroll
            for (int p = 0; p < 2; p++) {
                int ml = wm*64 + mi*16 + gid + p*8;
                int m = m0 + ml;
                if (m >= cnt) continue;
                size_t slot = (size_t)base + m;
                #pragma unroll
                for (int ni = 0; ni < 4; ni++) {
                    int nl = wn*32 + ni*8 + tig*2;
                    int col = n0 + nl;
                    float2 v3 = *reinterpret_cast<const float2*>(xch + ml*66 + nl);
                    float a0 = acc[mi][ni][2*p], a1 = acc[mi][ni][2*p+1];
                    float h0 = a0 * (1.f/(1.f+__expf(-a0))) * v3.x;
                    float h1 = a1 * (1.f/(1.f+__expf(-a1))) * v3.y;
                    store2h(g_h + slot*HS + col, __float2half(h0), __float2half(h1));
                }
            }
    }
}

// ---------------- GEMM2: out += w * (h W2^T)  (fused combine) ----------------
// CTA 128x128, 8 warps 2x4, warp tile 64x32, KC=64, 3-stage, 2 CTAs/SM.
__global__ __launch_bounds__(256, 2) void gemm2_mma(float* __restrict__ out) {
    int e   = blockIdx.z;
    int cnt = g_counts[e];
    int m0  = blockIdx.y * 128;
    if (m0 >= cnt) return;
    int base = g_offsets[e];
    int n0   = blockIdx.x * 128;

    extern __shared__ char smem[];
    uint32_t sm = smem_u32(smem);
    int tid = threadIdx.x, wid = tid >> 5, lane = tid & 31;
    int wm = wid & 1, wn = wid >> 1;

    const __half* A = g_h  + (size_t)(base + m0) * HS;
    const __half* B = g_w2 + ((size_t)e * DIM + n0) * HS;

    float acc[4][4][4];
    #pragma unroll
    for (int i = 0; i < 4; i++)
        #pragma unroll
        for (int j = 0; j < 4; j++)
            #pragma unroll
            for (int r = 0; r < 4; r++) acc[i][j][r] = 0.f;

    const int NC = HS / KC;   // 43

    #pragma unroll
    for (int pc = 0; pc < 2; pc++) {
        uint32_t sb = sm + pc * G2_STAGE;
        int k0 = pc * KC;
        cp_tile128(sb,          A + k0, HS, tid);
        cp_tile128(sb + TILE_A, B + k0, HS, tid);
        CP_COMMIT();
    }

    for (int c = 0; c < NC; c++) {
        if (c + 1 < NC) CP_WAIT1(); else CP_WAIT0();
        __syncthreads();
        if (c + 2 < NC) {
            uint32_t sb = sm + ((c + 2) % 3) * G2_STAGE;
            int k0 = (c + 2) * KC;
            cp_tile128(sb,          A + k0, HS, tid);
            cp_tile128(sb + TILE_A, B + k0, HS, tid);
            CP_COMMIT();
        }

        uint32_t sb = sm + (c % 3) * G2_STAGE;
        uint32_t sA = sb, sB = sb + TILE_A;

        #pragma unroll
        for (int ks = 0; ks < 4; ks++) {
            int kk = ks * 16;
            uint32_t aoff = (uint32_t)(wm*64 + (lane & 15)) * (SROW*2)
                          + (uint32_t)(kk + (lane >> 4) * 8) * 2;
            uint32_t af[4][4];
            #pragma unroll
            for (int mi = 0; mi < 4; mi++)
                ldsm4(af[mi], sA + aoff + mi*16*(SROW*2));
            uint32_t boff = (uint32_t)(wn*32 + ((lane >> 4) & 1)*8 + (lane & 7)) * (SROW*2)
                          + (uint32_t)(kk + ((lane >> 3) & 1)*8) * 2;
            uint32_t bf[8];
            ldsm4(&bf[0], sB + boff);
            ldsm4(&bf[4], sB + boff + 16*(SROW*2));
            #pragma unroll
            for (int mi = 0; mi < 4; mi++)
                #pragma unroll
                for (int ni = 0; ni < 4; ni++)
                    mma16816(acc[mi][ni], af[mi], &bf[ni*2]);
        }
    }

    // fused combine epilogue: out[tok] += w * y   (REDG, no return)
    int gid = lane >> 2, tig = lane & 3;
    #pragma unroll
    for (int mi = 0; mi < 4; mi++) {
        #pragma unroll
        for (int p = 0; p < 2; p++) {
            int m = m0 + wm*64 + mi*16 + gid + p*8;
            if (m >= cnt) continue;
            int slot = base + m;
            int tok  = g_perm[slot];
            float w  = g_slotW[slot];
            float* orow = out + (size_t)tok * DIM;
            #pragma unroll
            for (int ni = 0; ni < 4; ni++) {
                int col = n0 + wn*32 + ni*8 + tig*2;
                atomicAdd(orow + col,     w * acc[mi][ni][2*p]);
                atomicAdd(orow + col + 1, w * acc[mi][ni][2*p+1]);
            }
        }
    }
}

// ---------------- launch ----------------
extern "C" void kernel_launch(void* const* d_in, const int* in_sizes, int n_in,
                              void* d_out, int out_size) {
    const float* x  = (const float*)d_in[0];
    const float* gw = (const float*)d_in[1];
    const float* w1 = (const float*)d_in[2];
    const float* w2 = (const float*)d_in[3];
    const float* w3 = (const float*)d_in[4];
    float* out = (float*)d_out;

    cudaFuncSetAttribute(gemm1_mma, cudaFuncAttributeMaxDynamicSharedMemorySize, G1_SMEM);
    cudaFuncSetAttribute(gemm2_mma, cudaFuncAttributeMaxDynamicSharedMemorySize, G2_SMEM);

    init_kernel<<<1, 256>>>();
    zero_out_kernel<<<OUT_ELEMS/1024, 256>>>(out);
    convert_w13_kernel<<<dim3(NE*HP, 2), 256>>>(w1, w3);
    convert_w2_kernel<<<NE*DIM, 256>>>(w2);
    router_kernel<<<TOKENS/8, 256>>>(x, gw);
    offsets_kernel<<<1, 32>>>();
    aux_kernel<<<1, 32>>>(out, out_size);
    scatter_kernel<<<(TOKENS+255)/256, 256>>>();
    gather_x_kernel<<<MAXROWS, 256>>>(x);
    gemm1_mma<<<dim3(HS/64, TOKENS/128, NE), 256, G1_SMEM>>>();
    gemm2_mma<<<dim3(DIM/128, TOKENS/128, NE), 256, G2_SMEM>>>(out);
}

// round 16
// speedup vs baseline: 1.0680x; 1.0680x over previous
#include <cuda_runtime.h>
#include <cuda_fp16.h>
#include <cstdint>
#include <math.h>

// ---------------- problem constants ----------------
#define TOKENS   8192
#define DIM      1024
#define NE       8
#define TOPK     2
#define HID      2730
#define HS       2752          // padded K for GEMM2 / N for GEMM1 (43*64)
#define HP       2816          // padded row count for w1/w3 (22*128)
#define ASSIGN   (TOKENS*TOPK)
#define MAXROWS  (ASSIGN+128)
#define OUT_ELEMS ((size_t)TOKENS*DIM)

#define KC     64              // K elements per chunk (4 mma k-steps)
#define SROW   72              // smem row stride (elements) -> 144B, conflict-free ldmatrix
#define TILE_A (128*SROW*2)    // 18432 B : 128x64 fp16 tile
#define TILE_Bv (64*SROW*2)    // 9216 B  : 64x64 fp16 tile
#define G1_STAGE (TILE_A + 2*TILE_Bv)   // A + B1 + B3 = 36864
#define G1_SMEM  (2*G1_STAGE)           // 73728 (2 CTAs/SM)
#define G2_STAGE (2*TILE_A)             // A + B = 36864
#define G2_SMEM  (2*G2_STAGE)           // 73728

// ---------------- device scratch ----------------
__device__ int   g_counts[NE];
__device__ int   g_cursor[NE];
__device__ int   g_offsets[NE+1];
__device__ float g_probSums[NE];
__device__ int   g_eids[ASSIGN];
__device__ float g_wts[ASSIGN];
__device__ int   g_perm[ASSIGN];
__device__ int   g_slotOf[ASSIGN];
__device__ float g_slotW[ASSIGN];
__device__ __half g_x[(size_t)MAXROWS*DIM];
__device__ __half g_w1[(size_t)NE*HP*DIM];
__device__ __half g_w3[(size_t)NE*HP*DIM];
__device__ __half g_w2[(size_t)NE*DIM*HS];
__device__ __half g_h[(size_t)MAXROWS*HS];
__device__ float g_y[(size_t)ASSIGN*DIM];

// ---------------- helpers ----------------
__device__ __forceinline__ uint32_t smem_u32(const void* p) {
    uint32_t a;
    asm("{ .reg .u64 t; cvta.to.shared.u64 t, %1; cvt.u32.u64 %0, t; }"
        : "=r"(a) : "l"(p));
    return a;
}
__device__ __forceinline__ void cp16(uint32_t dst, const void* src) {
    asm volatile("cp.async.cg.shared.global [%0], [%1], 16;" :: "r"(dst), "l"(src));
}
#define CP_COMMIT() asm volatile("cp.async.commit_group;" ::: "memory")
#define CP_WAIT0()  asm volatile("cp.async.wait_group 0;" ::: "memory")

__device__ __forceinline__ void ldsm4(uint32_t* r, uint32_t addr) {
    asm volatile("ldmatrix.sync.aligned.m8n8.x4.shared.b16 {%0,%1,%2,%3}, [%4];"
                 : "=r"(r[0]), "=r"(r[1]), "=r"(r[2]), "=r"(r[3]) : "r"(addr));
}
__device__ __forceinline__ void mma16816(float* c, const uint32_t* a, const uint32_t* b) {
    asm volatile("mma.sync.aligned.m16n8k16.row.col.f32.f16.f16.f32 "
                 "{%0,%1,%2,%3}, {%4,%5,%6,%7}, {%8,%9}, {%0,%1,%2,%3};"
                 : "+f"(c[0]), "+f"(c[1]), "+f"(c[2]), "+f"(c[3])
                 : "r"(a[0]), "r"(a[1]), "r"(a[2]), "r"(a[3]),
                   "r"(b[0]), "r"(b[1]));
}

// 128x64 fp16 tile (row-major, stride SROW) via cp.async : 1024 cp16, 4/thread
__device__ __forceinline__ void cp_tile128(uint32_t s, const __half* g,
                                           int rstride, int t) {
    #pragma unroll
    for (int i = 0; i < 4; i++) {
        int id = t + i*256;
        int row = id >> 3, c16 = id & 7;
        cp16(s + (uint32_t)row*(SROW*2) + (uint32_t)c16*16,
             (const char*)g + (size_t)row*rstride*2 + (size_t)c16*16);
    }
}
// 64x64 fp16 tile : 512 cp16, 2/thread
__device__ __forceinline__ void cp_tile64(uint32_t s, const __half* g,
                                          int rstride, int t) {
    #pragma unroll
    for (int i = 0; i < 2; i++) {
        int id = t + i*256;
        int row = id >> 3, c16 = id & 7;
        cp16(s + (uint32_t)row*(SROW*2) + (uint32_t)c16*16,
             (const char*)g + (size_t)row*rstride*2 + (size_t)c16*16);
    }
}

__device__ __forceinline__ void store2h(__half* p, __half a, __half b) {
    __half2 v; v.x = a; v.y = b;
    *reinterpret_cast<__half2*>(p) = v;
}

// ---------------- router ----------------
__global__ __launch_bounds__(256) void router_kernel(const float* __restrict__ x,
                                                     const float* __restrict__ gw) {
    __shared__ float sgw[NE*DIM];
    __shared__ float sprob[8][NE];
    for (int i = threadIdx.x; i < NE*DIM; i += 256) sgw[i] = gw[i];
    __syncthreads();
    int warp = threadIdx.x >> 5, lane = threadIdx.x & 31;
    int tok = blockIdx.x * 8 + warp;
    const float* xr = x + (size_t)tok * DIM;
    float acc[NE];
    #pragma unroll
    for (int e = 0; e < NE; e++) acc[e] = 0.f;
    for (int d = lane; d < DIM; d += 32) {
        float xv = xr[d];
        #pragma unroll
        for (int e = 0; e < NE; e++) acc[e] += xv * sgw[e*DIM + d];
    }
    #pragma unroll
    for (int e = 0; e < NE; e++)
        #pragma unroll
        for (int o = 16; o > 0; o >>= 1)
            acc[e] += __shfl_xor_sync(0xffffffffu, acc[e], o);
    if (lane == 0) {
        float mx = acc[0];
        #pragma unroll
        for (int e = 1; e < NE; e++) mx = fmaxf(mx, acc[e]);
        float p[NE], s = 0.f;
        #pragma unroll
        for (int e = 0; e < NE; e++) { p[e] = expf(acc[e] - mx); s += p[e]; }
        float inv = 1.f / s;
        #pragma unroll
        for (int e = 0; e < NE; e++) p[e] *= inv;
        int i0 = 0;
        #pragma unroll
        for (int e = 1; e < NE; e++) if (p[e] > p[i0]) i0 = e;
        int i1 = (i0 == 0) ? 1 : 0;
        #pragma unroll
        for (int e = 0; e < NE; e++) if (e != i0 && p[e] > p[i1]) i1 = e;
        float ws = 1.f / (p[i0] + p[i1]);
        g_eids[2*tok]   = i0; g_wts[2*tok]   = p[i0] * ws;
        g_eids[2*tok+1] = i1; g_wts[2*tok+1] = p[i1] * ws;
        atomicAdd(&g_counts[i0], 1);
        atomicAdd(&g_counts[i1], 1);
        #pragma unroll
        for (int e = 0; e < NE; e++) sprob[warp][e] = p[e];
    }
    __syncthreads();
    if (threadIdx.x < NE) {
        float s = 0.f;
        #pragma unroll
        for (int w = 0; w < 8; w++) s += sprob[w][threadIdx.x];
        atomicAdd(&g_probSums[threadIdx.x], s);
    }
}

__global__ void offsets_kernel() {
    if (threadIdx.x == 0) {
        int s = 0;
        for (int e = 0; e < NE; e++) { g_offsets[e] = s; s += g_counts[e]; }
        g_offsets[NE] = s;
    }
}

__global__ void aux_kernel(float* out, int out_size) {
    if (threadIdx.x == 0 && (size_t)out_size > OUT_ELEMS) {
        float s = 0.f;
        for (int e = 0; e < NE; e++) {
            float d = g_probSums[e] * (1.f / TOKENS) - (1.f / NE);
            s += d * d;
        }
        out[OUT_ELEMS] = 0.01f * (s / NE);
    }
}

__global__ void scatter_kernel() {
    int tok = blockIdx.x * 256 + threadIdx.x;
    if (tok >= TOKENS) return;
    #pragma unroll
    for (int k = 0; k < TOPK; k++) {
        int e = g_eids[2*tok + k];
        int pos = atomicAdd(&g_cursor[e], 1);
        int slot = g_offsets[e] + pos;
        g_perm[slot]  = tok;
        g_slotW[slot] = g_wts[2*tok + k];
        g_slotOf[2*tok + k] = slot;
    }
}

// ---------------- conversion pre-passes ----------------
// w1/w3 -> padded [NE][HP][DIM] fp16; block (0,0) also does the init reset
__global__ __launch_bounds__(256) void convert_w13_kernel(const float* __restrict__ w1,
                                                          const float* __restrict__ w3) {
    if (blockIdx.x == 0 && blockIdx.y == 0 && threadIdx.x < NE) {
        g_counts[threadIdx.x] = 0;
        g_cursor[threadIdx.x] = 0;
        g_probSums[threadIdx.x] = 0.f;
    }
    size_t row = blockIdx.x;            // 0..NE*HP-1
    int e = (int)(row / HP), r = (int)(row % HP);
    const float* src = (blockIdx.y == 0) ? w1 : w3;
    __half* dsth = (blockIdx.y == 0) ? g_w1 : g_w3;
    size_t dst = row * DIM + threadIdx.x * 4;
    __half h[4];
    if (r < HID) {
        float4 v = *reinterpret_cast<const float4*>(src + ((size_t)e*HID + r)*DIM + threadIdx.x*4);
        h[0] = __float2half(v.x); h[1] = __float2half(v.y);
        h[2] = __float2half(v.z); h[3] = __float2half(v.w);
    } else {
        #pragma unroll
        for (int i = 0; i < 4; i++) h[i] = __float2half(0.f);
    }
    store2h(dsth + dst, h[0], h[1]); store2h(dsth + dst + 2, h[2], h[3]);
}

// w2 [NE][DIM][HID] -> padded [NE][DIM][HS] fp16; vectorized (float2 -> half2)
__global__ __launch_bounds__(256) void convert_w2_kernel(const float* __restrict__ w2) {
    size_t row = blockIdx.x;            // 0..NE*DIM-1
    const float* src = w2 + row * HID;          // 8B-aligned (HID*4 = 10920)
    __half* dst = g_w2 + row * HS;              // 4B-aligned (HS*2 = 5504)
    // 1376 half2 slots per row; HID/2 = 1365 full float2 reads
    for (int s2 = threadIdx.x; s2 < HS/2; s2 += 256) {
        __half2 v;
        if (s2 < HID/2) {
            float2 f = *reinterpret_cast<const float2*>(src + s2*2);
            v = __floats2half2_rn(f.x, f.y);
        } else {
            v = __floats2half2_rn(0.f, 0.f);
        }
        *reinterpret_cast<__half2*>(dst + s2*2) = v;
    }
}

// gather x rows by perm into fp16 (pad rows -> zero)
__global__ __launch_bounds__(256) void gather_x_kernel(const float* __restrict__ x) {
    int slot = blockIdx.x;
    size_t dst = (size_t)slot * DIM + threadIdx.x * 4;
    __half h[4];
    if (slot < ASSIGN) {
        int tok = g_perm[slot];
        float4 v = *reinterpret_cast<const float4*>(x + (size_t)tok*DIM + threadIdx.x*4);
        h[0] = __float2half(v.x); h[1] = __float2half(v.y);
        h[2] = __float2half(v.z); h[3] = __float2half(v.w);
    } else {
        #pragma unroll
        for (int i = 0; i < 4; i++) h[i] = __float2half(0.f);
    }
    store2h(g_x + dst, h[0], h[1]); store2h(g_x + dst + 2, h[2], h[3]);
}

__global__ void padh_kernel() {
    size_t r = ASSIGN + blockIdx.x;
    for (int c = threadIdx.x; c < HS; c += 256)
        g_h[r*HS + c] = __float2half(0.f);
}

// ---------------- GEMM1: h = silu(X W1^T) * (X W3^T) ----------------
// CTA 128x64, warps 0-3 w1 / 4-7 w3, warp tile 64x32, KC=64,
// 2-stage cp.async, ONE barrier per chunk, 2 CTAs/SM.
__global__ __launch_bounds__(256, 2) void gemm1_mma() {
    int e   = blockIdx.z;
    int cnt = g_counts[e];
    int m0  = blockIdx.y * 128;
    if (m0 >= cnt) return;
    int base = g_offsets[e];
    int n0   = blockIdx.x * 64;

    extern __shared__ char smem[];
    uint32_t sm = smem_u32(smem);
    int tid = threadIdx.x, wid = tid >> 5, lane = tid & 31;
    int prod = wid >> 2, wm = wid & 1, wn = (wid >> 1) & 1;

    const __half* A  = g_x  + (size_t)(base + m0) * DIM;
    const __half* B1 = g_w1 + ((size_t)e * HP + n0) * DIM;
    const __half* B3 = g_w3 + ((size_t)e * HP + n0) * DIM;

    float acc[4][4][4];
    #pragma unroll
    for (int i = 0; i < 4; i++)
        #pragma unroll
        for (int j = 0; j < 4; j++)
            #pragma unroll
            for (int r = 0; r < 4; r++) acc[i][j][r] = 0.f;

    const int NC = DIM / KC;   // 16

    {   // preload chunk 0 -> stage 0
        cp_tile128(sm,                      A,  DIM, tid);
        cp_tile64 (sm + TILE_A,             B1, DIM, tid);
        cp_tile64 (sm + TILE_A + TILE_Bv,   B3, DIM, tid);
        CP_COMMIT();
    }

    for (int c = 0; c < NC; c++) {
        CP_WAIT0();
        __syncthreads();                    // single barrier per chunk
        if (c + 1 < NC) {
            uint32_t sb = sm + ((c + 1) & 1) * G1_STAGE;
            int k0 = (c + 1) * KC;
            cp_tile128(sb,                    A  + k0, DIM, tid);
            cp_tile64 (sb + TILE_A,           B1 + k0, DIM, tid);
            cp_tile64 (sb + TILE_A + TILE_Bv, B3 + k0, DIM, tid);
            CP_COMMIT();
        }

        uint32_t sb = sm + (c & 1) * G1_STAGE;
        uint32_t sA = sb;
        uint32_t sB = sb + TILE_A + (uint32_t)prod * TILE_Bv;

        #pragma unroll
        for (int ks = 0; ks < 4; ks++) {
            int kk = ks * 16;
            uint32_t aoff = (uint32_t)(wm*64 + (lane & 15)) * (SROW*2)
                          + (uint32_t)(kk + (lane >> 4) * 8) * 2;
            uint32_t af[4][4];
            #pragma unroll
            for (int mi = 0; mi < 4; mi++)
                ldsm4(af[mi], sA + aoff + mi*16*(SROW*2));
            uint32_t boff = (uint32_t)(wn*32 + ((lane >> 4) & 1)*8 + (lane & 7)) * (SROW*2)
                          + (uint32_t)(kk + ((lane >> 3) & 1)*8) * 2;
            uint32_t bf[8];
            ldsm4(&bf[0], sB + boff);
            ldsm4(&bf[4], sB + boff + 16*(SROW*2));
            #pragma unroll
            for (int mi = 0; mi < 4; mi++)
                #pragma unroll
                for (int ni = 0; ni < 4; ni++)
                    mma16816(acc[mi][ni], af[mi], &bf[ni*2]);
        }
    }

    // protect last-chunk smem reads, then exchange w3 product through smem
    __syncthreads();
    float* xch = reinterpret_cast<float*>(smem);   // 128 x 66 f32 = 33792 B
    int gid = lane >> 2, tig = lane & 3;
    if (prod == 1) {
        #pragma unroll
        for (int mi = 0; mi < 4; mi++)
            #pragma unroll
            for (int p = 0; p < 2; p++) {
                int ml = wm*64 + mi*16 + gid + p*8;
                #pragma unroll
                for (int ni = 0; ni < 4; ni++) {
                    int nl = wn*32 + ni*8 + tig*2;
                    *reinterpret_cast<float2*>(xch + ml*66 + nl) =
                        make_float2(acc[mi][ni][2*p], acc[mi][ni][2*p+1]);
                }
            }
    }
    __syncthreads();
    if (prod == 0) {
        #pragma unroll
        for (int mi = 0; mi < 4; mi++)
            #pragma unroll
            for (int p = 0; p < 2; p++) {
                int ml = wm*64 + mi*16 + gid + p*8;
                int m = m0 + ml;
                if (m >= cnt) continue;
                size_t slot = (size_t)base + m;
                #pragma unroll
                for (int ni = 0; ni < 4; ni++) {
                    int nl = wn*32 + ni*8 + tig*2;
                    int col = n0 + nl;
                    float2 v3 = *reinterpret_cast<const float2*>(xch + ml*66 + nl);
                    float a0 = acc[mi][ni][2*p], a1 = acc[mi][ni][2*p+1];
                    float h0 = a0 * (1.f/(1.f+__expf(-a0))) * v3.x;
                    float h1 = a1 * (1.f/(1.f+__expf(-a1))) * v3.y;
                    store2h(g_h + slot*HS + col, __float2half(h0), __float2half(h1));
                }
            }
    }
}

// ---------------- GEMM2: y = h W2^T ----------------
// CTA 128x128, 8 warps 2x4, warp tile 64x32, KC=64, one barrier/chunk, 2 CTAs/SM.
__global__ __launch_bounds__(256, 2) void gemm2_mma() {
    int e   = blockIdx.z;
    int cnt = g_counts[e];
    int m0  = blockIdx.y * 128;
    if (m0 >= cnt) return;
    int base = g_offsets[e];
    int n0   = blockIdx.x * 128;

    extern __shared__ char smem[];
    uint32_t sm = smem_u32(smem);
    int tid = threadIdx.x, wid = tid >> 5, lane = tid & 31;
    int wm = wid & 1, wn = wid >> 1;

    const __half* A = g_h  + (size_t)(base + m0) * HS;
    const __half* B = g_w2 + ((size_t)e * DIM + n0) * HS;

    float acc[4][4][4];
    #pragma unroll
    for (int i = 0; i < 4; i++)
        #pragma unroll
        for (int j = 0; j < 4; j++)
            #pragma unroll
            for (int r = 0; r < 4; r++) acc[i][j][r] = 0.f;

    const int NC = HS / KC;   // 43

    {
        cp_tile128(sm,          A, HS, tid);
        cp_tile128(sm + TILE_A, B, HS, tid);
        CP_COMMIT();
    }

    for (int c = 0; c < NC; c++) {
        CP_WAIT0();
        __syncthreads();
        if (c + 1 < NC) {
            uint32_t sb = sm + ((c + 1) & 1) * G2_STAGE;
            int k0 = (c + 1) * KC;
            cp_tile128(sb,          A + k0, HS, tid);
            cp_tile128(sb + TILE_A, B + k0, HS, tid);
            CP_COMMIT();
        }

        uint32_t sb = sm + (c & 1) * G2_STAGE;
        uint32_t sA = sb, sB = sb + TILE_A;

        #pragma unroll
        for (int ks = 0; ks < 4; ks++) {
            int kk = ks * 16;
            uint32_t aoff = (uint32_t)(wm*64 + (lane & 15)) * (SROW*2)
                          + (uint32_t)(kk + (lane >> 4) * 8) * 2;
            uint32_t af[4][4];
            #pragma unroll
            for (int mi = 0; mi < 4; mi++)
                ldsm4(af[mi], sA + aoff + mi*16*(SROW*2));
            uint32_t boff = (uint32_t)(wn*32 + ((lane >> 4) & 1)*8 + (lane & 7)) * (SROW*2)
                          + (uint32_t)(kk + ((lane >> 3) & 1)*8) * 2;
            uint32_t bf[8];
            ldsm4(&bf[0], sB + boff);
            ldsm4(&bf[4], sB + boff + 16*(SROW*2));
            #pragma unroll
            for (int mi = 0; mi < 4; mi++)
                #pragma unroll
                for (int ni = 0; ni < 4; ni++)
                    mma16816(acc[mi][ni], af[mi], &bf[ni*2]);
        }
    }

    int gid = lane >> 2, tig = lane & 3;
    #pragma unroll
    for (int mi = 0; mi < 4; mi++) {
        #pragma unroll
        for (int p = 0; p < 2; p++) {
            int m = m0 + wm*64 + mi*16 + gid + p*8;
            if (m >= cnt) continue;
            size_t slot = (size_t)base + m;
            #pragma unroll
            for (int ni = 0; ni < 4; ni++) {
                int col = n0 + wn*32 + ni*8 + tig*2;
                float2 v = make_float2(acc[mi][ni][2*p], acc[mi][ni][2*p+1]);
                *reinterpret_cast<float2*>(g_y + slot*DIM + col) = v;
            }
        }
    }
}

// ---------------- combine ----------------
__global__ void combine_kernel(float* __restrict__ out) {
    int tok = blockIdx.x;
    int c = threadIdx.x * 4;
    int s0 = g_slotOf[2*tok], s1 = g_slotOf[2*tok+1];
    float w0 = g_slotW[s0], w1 = g_slotW[s1];
    float4 y0 = *reinterpret_cast<const float4*>(g_y + (size_t)s0*DIM + c);
    float4 y1 = *reinterpret_cast<const float4*>(g_y + (size_t)s1*DIM + c);
    float4 o;
    o.x = w0*y0.x + w1*y1.x;
    o.y = w0*y0.y + w1*y1.y;
    o.z = w0*y0.z + w1*y1.z;
    o.w = w0*y0.w + w1*y1.w;
    *reinterpret_cast<float4*>(out + (size_t)tok*DIM + c) = o;
}

// ---------------- launch ----------------
extern "C" void kernel_launch(void* const* d_in, const int* in_sizes, int n_in,
                              void* d_out, int out_size) {
    const float* x  = (const float*)d_in[0];
    const float* gw = (const float*)d_in[1];
    const float* w1 = (const float*)d_in[2];
    const float* w2 = (const float*)d_in[3];
    const float* w3 = (const float*)d_in[4];
    float* out = (float*)d_out;

    cudaFuncSetAttribute(gemm1_mma, cudaFuncAttributeMaxDynamicSharedMemorySize, G1_SMEM);
    cudaFuncSetAttribute(gemm2_mma, cudaFuncAttributeMaxDynamicSharedMemorySize, G2_SMEM);

    convert_w13_kernel<<<dim3(NE*HP, 2), 256>>>(w1, w3);   // also resets counters
    convert_w2_kernel<<<NE*DIM, 256>>>(w2);
    router_kernel<<<TOKENS/8, 256>>>(x, gw);
    offsets_kernel<<<1, 32>>>();
    aux_kernel<<<1, 32>>>(out, out_size);
    scatter_kernel<<<(TOKENS+255)/256, 256>>>();
    gather_x_kernel<<<MAXROWS, 256>>>(x);
    padh_kernel<<<128, 256>>>();
    gemm1_mma<<<dim3(HS/64, TOKENS/128, NE), 256, G1_SMEM>>>();
    gemm2_mma<<<dim3(DIM/128, TOKENS/128, NE), 256, G2_SMEM>>>();
    combine_kernel<<<TOKENS, 256>>>(out);
}